// round 10
// baseline (speedup 1.0000x reference)
#include <cuda_runtime.h>
#include <cuda_fp16.h>
#include <cstdint>
#include <math.h>

// ---------------- Problem constants ----------------
#define D_DIM 4096
#define S_DIM 2048
#define B_DIM 4
#define K_EXP 8
#define R_DIM 16
#define KR    128
#define T_TOK 8192
#define SCALE 2.0f
#define NCHUNK 32          // mean-pool chunks (64 rows each)

// ---------------- Device scratch (static; no runtime alloc) ----------------
__device__ __align__(16) float  g_partial[B_DIM * NCHUNK * D_DIM];    // 2 MB
__device__ __align__(16) float  g_lp[B_DIM * 16 * K_EXP];             // partial logits
__device__ __align__(16) __half g_xh[(size_t)T_TOK * D_DIM];          // 64 MB
__device__ __align__(16) __half g_wh[(size_t)D_DIM * D_DIM];          // 32 MB
__device__ __align__(16) __half g_ah[(size_t)KR * D_DIM];             //  1 MB
__device__ __align__(16) __half g_Bwh[(size_t)B_DIM * D_DIM * KR];    //  4 MB
__device__ __align__(16) __half g_hh[(size_t)T_TOK * KR];             //  2 MB
__device__ __align__(16) float  g_hp[2][(size_t)T_TOK * KR];          //  8 MB

// ---------------- PTX helpers ----------------
__device__ __forceinline__ uint32_t smem_u32(const void* p) {
    uint32_t a;
    asm("{ .reg .u64 t; cvta.to.shared.u64 t, %1; cvt.u32.u64 %0, t; }"
        : "=r"(a) : "l"(p));
    return a;
}

#define CP_ASYNC16(dst, src) \
    asm volatile("cp.async.cg.shared.global [%0], [%1], 16;" \
                 :: "r"(dst), "l"(src) : "memory")
#define CP_COMMIT() asm volatile("cp.async.commit_group;" ::: "memory")
#define CP_WAIT(n)  asm volatile("cp.async.wait_group %0;" :: "n"(n) : "memory")

#define LDSM4(r0, r1, r2, r3, addr) \
    asm volatile("ldmatrix.sync.aligned.m8n8.x4.shared.b16 {%0,%1,%2,%3}, [%4];" \
                 : "=r"(r0), "=r"(r1), "=r"(r2), "=r"(r3) : "r"(addr))

#define MMA16816(d, a, b) \
    asm volatile("mma.sync.aligned.m16n8k16.row.col.f32.f16.f16.f32 " \
                 "{%0,%1,%2,%3},{%4,%5,%6,%7},{%8,%9},{%0,%1,%2,%3};" \
                 : "+f"((d)[0]), "+f"((d)[1]), "+f"((d)[2]), "+f"((d)[3]) \
                 : "r"((a)[0]), "r"((a)[1]), "r"((a)[2]), "r"((a)[3]), \
                   "r"((b)[0]), "r"((b)[1]))

// SW128 swizzle for 128-byte rows
__device__ __forceinline__ uint32_t sw128(uint32_t base, int row, int ch) {
    uint32_t off = (uint32_t)(row * 128 + ch * 16);
    return base + (off ^ ((off >> 3) & 0x70));
}

// ---------------------------------------------------------------------------
// Aux kernels
// ---------------------------------------------------------------------------
__global__ void cvt_f2h_kernel(const float* __restrict__ s, __half* __restrict__ d) {
    size_t i = ((size_t)blockIdx.x * 256 + threadIdx.x) * 4;
    float4 v = *(const float4*)(s + i);
    *(__half2*)(d + i)     = __floats2half2_rn(v.x, v.y);
    *(__half2*)(d + i + 2) = __floats2half2_rn(v.z, v.w);
}

// Fused x fp32->fp16 + column partial sums over 64-row chunks.
__global__ void cvt_mean_kernel(const float* __restrict__ x, __half* __restrict__ xh) {
    int d0 = blockIdx.x * 1024 + threadIdx.x * 4;
    int b  = blockIdx.y;
    int c  = blockIdx.z;
    size_t base = ((size_t)(b * S_DIM + c * 64)) * D_DIM + d0;
    float s0 = 0.f, s1 = 0.f, s2 = 0.f, s3 = 0.f;
#pragma unroll 4
    for (int i = 0; i < 64; i++) {
        float4 v = *(const float4*)(x + base + (size_t)i * D_DIM);
        s0 += v.x; s1 += v.y; s2 += v.z; s3 += v.w;
        *(__half2*)(xh + base + (size_t)i * D_DIM)     = __floats2half2_rn(v.x, v.y);
        *(__half2*)(xh + base + (size_t)i * D_DIM + 2) = __floats2half2_rn(v.z, v.w);
    }
    float4 s = { s0, s1, s2, s3 };
    *(float4*)(g_partial + (b * NCHUNK + c) * D_DIM + d0) = s;
}

// Router phase A: partial logits per (b, slice of 256 d-columns)
__global__ void router_a_kernel(const float* __restrict__ rw) {
    int b = blockIdx.x;
    int s = blockIdx.y;
    int tid = threadIdx.x;
    int d = s * 256 + tid;

    float m = 0.f;
#pragma unroll
    for (int c = 0; c < NCHUNK; c++) m += g_partial[(b * NCHUNK + c) * D_DIM + d];
    m *= (1.0f / (float)S_DIM);

    __shared__ float red[256];
#pragma unroll
    for (int k = 0; k < K_EXP; k++) {
        red[tid] = m * rw[k * D_DIM + d];
        __syncthreads();
#pragma unroll
        for (int off = 128; off > 0; off >>= 1) {
            if (tid < off) red[tid] += red[tid + off];
            __syncthreads();
        }
        if (tid == 0) g_lp[(b * 16 + s) * K_EXP + k] = red[0];
        __syncthreads();
    }
}

// bw_kernel with fused softmax: each block recomputes the 4x8 router softmax
// from g_lp (8-lane shfl groups), then scales lora_B.
__global__ void bw_kernel(const float* __restrict__ loraB, const float* __restrict__ rb) {
    __shared__ float w[B_DIM * K_EXP];
    if (threadIdx.x < 32) {
        int t = threadIdx.x;
        int b = t >> 3, k = t & 7;
        float s = 0.f;
#pragma unroll
        for (int q = 0; q < 16; q++) s += g_lp[(b * 16 + q) * K_EXP + k];
        s += rb[k];
        // softmax within each 8-lane group (xor 1,2,4 stays in-group)
        float mx = s;
#pragma unroll
        for (int off = 4; off > 0; off >>= 1)
            mx = fmaxf(mx, __shfl_xor_sync(0xffffffffu, mx, off));
        float e = expf(s - mx);
        float sum = e;
#pragma unroll
        for (int off = 4; off > 0; off >>= 1)
            sum += __shfl_xor_sync(0xffffffffu, sum, off);
        w[t] = e / sum;
    }
    __syncthreads();

    int idx = blockIdx.x * 256 + threadIdx.x;           // < 2^21
    int b   = idx >> 19;
    int rem = idx & ((1 << 19) - 1);
    int o   = rem >> 7;
    int c   = rem & 127;
    int k   = c >> 4;
    int r   = c & 15;
    float v = SCALE * w[b * K_EXP + k] * loraB[(k * D_DIM + o) * R_DIM + r];
    g_Bwh[idx] = __float2half_rn(v);
}

__global__ void h_reduce_kernel() {
    size_t i = (size_t)blockIdx.x * 256 + threadIdx.x;
    float2 a = *(const float2*)(g_hp[0] + 2 * i);
    float2 b = *(const float2*)(g_hp[1] + 2 * i);
    *(__half2*)(g_hh + 2 * i) = __floats2half2_rn(a.x + b.x, a.y + b.y);
}

// ---------------------------------------------------------------------------
// h-GEMM: warp tile 64x32, BK=64, 3-stage, split-K z (R8 config, validated).
// ---------------------------------------------------------------------------
__global__ void __launch_bounds__(128, 2) h_gemm_kernel(
    const __half* __restrict__ A, const __half* __restrict__ Bm,
    float* __restrict__ outf, int iters)
{
    constexpr int BM = 64, BN = 128;
    constexpr int THREADS = 128;
    constexpr int ABYT = BM * 128;
    constexpr int STG  = (BM + BN) * 128;

    extern __shared__ __align__(128) char smem[];
    const uint32_t sbase = smem_u32(smem);
    const int tid  = threadIdx.x;
    const int lane = tid & 31;
    const int wid  = tid >> 5;
    const int wn   = wid;                  // 4 warps over N
    const int i0   = blockIdx.y * BM;
    const int zo   = blockIdx.z * iters * 64;
    A  += zo;
    Bm += zo;
    outf += (size_t)blockIdx.z * ((size_t)T_TOK * KR);

    auto loadst = [&](int git, int st) {
        uint32_t abase = sbase + st * STG;
        uint32_t bbase = abase + ABYT;
        int koff = git * 64;
#pragma unroll
        for (int t = 0; t < (BM * 8) / THREADS; t++) {
            int idx = tid + t * THREADS;
            int row = idx >> 3, ch = idx & 7;
            CP_ASYNC16(sw128(abase, row, ch),
                       A + (size_t)(i0 + row) * D_DIM + koff + ch * 8);
        }
#pragma unroll
        for (int t = 0; t < (BN * 8) / THREADS; t++) {
            int idx = tid + t * THREADS;
            int row = idx >> 3, ch = idx & 7;
            CP_ASYNC16(sw128(bbase, row, ch),
                       Bm + (size_t)row * D_DIM + koff + ch * 8);
        }
    };

    float acc[4][4][4];
#pragma unroll
    for (int mi = 0; mi < 4; mi++)
#pragma unroll
        for (int ni = 0; ni < 4; ni++)
#pragma unroll
            for (int e = 0; e < 4; e++) acc[mi][ni][e] = 0.f;

    loadst(0, 0); CP_COMMIT();
    loadst(1, 1); CP_COMMIT();

    int st = 0, pf = 2;
    for (int it = 0; it < iters; ++it) {
        CP_WAIT(1);
        __syncthreads();
        if (it + 2 < iters) loadst(it + 2, pf);
        CP_COMMIT();

        uint32_t sA = sbase + st * STG;
        uint32_t sB = sA + ABYT;
#pragma unroll
        for (int ks = 0; ks < 4; ks++) {
            int ch = ks * 2 + (lane >> 4);
            uint32_t a[4][4];
#pragma unroll
            for (int mi = 0; mi < 4; mi++) {
                int row = mi * 16 + (lane & 15);
                LDSM4(a[mi][0], a[mi][1], a[mi][2], a[mi][3], sw128(sA, row, ch));
            }
            uint32_t b[4][2];
#pragma unroll
            for (int j = 0; j < 2; j++) {
                int row = wn * 32 + j * 16 + (lane & 15);
                uint32_t t0, t1, t2, t3;
                LDSM4(t0, t1, t2, t3, sw128(sB, row, ch));
                b[2 * j][0]     = t0; b[2 * j][1]     = t2;
                b[2 * j + 1][0] = t1; b[2 * j + 1][1] = t3;
            }
#pragma unroll
            for (int mi = 0; mi < 4; mi++)
#pragma unroll
                for (int ni = 0; ni < 4; ni++)
                    MMA16816(acc[mi][ni], a[mi], b[ni]);
        }
        st = (st == 2) ? 0 : st + 1;
        pf = (pf == 2) ? 0 : pf + 1;
    }

#pragma unroll
    for (int mi = 0; mi < 4; mi++) {
        int r0 = i0 + mi * 16 + (lane >> 2);
#pragma unroll
        for (int ni = 0; ni < 4; ni++) {
            int c0 = wn * 32 + ni * 8 + 2 * (lane & 3);
            float2 v0 = { acc[mi][ni][0], acc[mi][ni][1] };
            float2 v1 = { acc[mi][ni][2], acc[mi][ni][3] };
            *(float2*)(outf + (size_t)r0 * KR + c0)       = v0;
            *(float2*)(outf + (size_t)(r0 + 8) * KR + c0) = v1;
        }
    }
}

// ---------------------------------------------------------------------------
// Main GEMM: BM=128, BN=128, BK=64, 4 warps (2x2 of 64x64), 128 threads,
// 3-stage ring (96 KB) -> 2 CTA/SM. Loader split into 4 quarters interleaved
// with the ks-steps to avoid front-batched L1tex queue bursts.
//   out = x@W^T (64 iters) + h@Bw^T (2 iters) + bias
// ---------------------------------------------------------------------------
__global__ void __launch_bounds__(128, 2) main_gemm_kernel(
    const __half* __restrict__ A,
    const __half* __restrict__ Bm,
    const __half* __restrict__ A2,
    const __half* __restrict__ B2all,
    const float* __restrict__ bias,
    float* __restrict__ outf)
{
    constexpr int BM = 128, BN = 128, THREADS = 128;
    constexpr int ITER0 = 64, ITERS = 66;
    constexpr int ABYT = BM * 128;           // 16 KB
    constexpr int STG  = (BM + BN) * 128;    // 32 KB

    extern __shared__ __align__(128) char smem[];
    const uint32_t sbase = smem_u32(smem);
    const int tid  = threadIdx.x;
    const int lane = tid & 31;
    const int wid  = tid >> 5;
    const int wm   = wid & 1;       // 2 warps over M (64 each)
    const int wn   = wid >> 1;      // 2 warps over N (64 each)
    const int i0   = blockIdx.y * BM;
    const int j0   = blockIdx.x * BN;
    const __half* B2 = B2all + (size_t)(i0 >> 11) * ((size_t)D_DIM * KR);

    // quarter-loader: quarter q issues A rows chunk 2q..2q+1 and B ditto
    auto loadstQ = [&](int git, int stg, int q) {
        uint32_t abase = sbase + stg * STG;
        uint32_t bbase = abase + ABYT;
        bool ph0 = (git < ITER0);
        int koff = ph0 ? git * 64 : (git - ITER0) * 64;
#pragma unroll
        for (int t = 2 * q; t < 2 * q + 2; t++) {
            int idx = tid + t * THREADS;
            int row = idx >> 3, ch = idx & 7;
            const __half* srcA = ph0
                ? A  + (size_t)(i0 + row) * D_DIM + koff + ch * 8
                : A2 + (size_t)(i0 + row) * KR   + koff + ch * 8;
            CP_ASYNC16(sw128(abase, row, ch), srcA);
            const __half* srcB = ph0
                ? Bm + (size_t)(j0 + row) * D_DIM + koff + ch * 8
                : B2 + (size_t)(j0 + row) * KR   + koff + ch * 8;
            CP_ASYNC16(sw128(bbase, row, ch), srcB);
        }
    };

    float acc[4][8][4];
#pragma unroll
    for (int mi = 0; mi < 4; mi++)
#pragma unroll
        for (int ni = 0; ni < 8; ni++)
#pragma unroll
            for (int e = 0; e < 4; e++) acc[mi][ni][e] = 0.f;

    // prologue: 2 stages in flight
#pragma unroll
    for (int q = 0; q < 4; q++) loadstQ(0, 0, q);
    CP_COMMIT();
#pragma unroll
    for (int q = 0; q < 4; q++) loadstQ(1, 1, q);
    CP_COMMIT();

    int st = 0, pf = 2;
    for (int it = 0; it < ITERS; ++it) {
        CP_WAIT(1);
        __syncthreads();

        uint32_t sA = sbase + st * STG;
        uint32_t sB = sA + ABYT;
        bool pre = (it + 2 < ITERS);
#pragma unroll
        for (int ks = 0; ks < 4; ks++) {
            if (pre) loadstQ(it + 2, pf, ks);
            int ch = ks * 2 + (lane >> 4);
            uint32_t a[4][4];
#pragma unroll
            for (int mi = 0; mi < 4; mi++) {
                int row = wm * 64 + mi * 16 + (lane & 15);
                LDSM4(a[mi][0], a[mi][1], a[mi][2], a[mi][3], sw128(sA, row, ch));
            }
            uint32_t b[8][2];
#pragma unroll
            for (int j = 0; j < 4; j++) {
                int row = wn * 64 + j * 16 + (lane & 15);
                uint32_t t0, t1, t2, t3;
                LDSM4(t0, t1, t2, t3, sw128(sB, row, ch));
                b[2 * j][0]     = t0; b[2 * j][1]     = t2;
                b[2 * j + 1][0] = t1; b[2 * j + 1][1] = t3;
            }
#pragma unroll
            for (int mi = 0; mi < 4; mi++)
#pragma unroll
                for (int ni = 0; ni < 8; ni++)
                    MMA16816(acc[mi][ni], a[mi], b[ni]);
        }
        CP_COMMIT();
        st = (st == 2) ? 0 : st + 1;
        pf = (pf == 2) ? 0 : pf + 1;
    }

    // epilogue: bias + write
#pragma unroll
    for (int mi = 0; mi < 4; mi++) {
        int r0 = i0 + wm * 64 + mi * 16 + (lane >> 2);
#pragma unroll
        for (int ni = 0; ni < 8; ni++) {
            int c0 = j0 + wn * 64 + ni * 8 + 2 * (lane & 3);
            float b0 = bias[c0], b1 = bias[c0 + 1];
            float2 v0 = { acc[mi][ni][0] + b0, acc[mi][ni][1] + b1 };
            float2 v1 = { acc[mi][ni][2] + b0, acc[mi][ni][3] + b1 };
            *(float2*)(outf + (size_t)r0 * D_DIM + c0)       = v0;
            *(float2*)(outf + (size_t)(r0 + 8) * D_DIM + c0) = v1;
        }
    }
}

// ---------------------------------------------------------------------------
extern "C" void kernel_launch(void* const* d_in, const int* in_sizes, int n_in,
                              void* d_out, int out_size) {
    const float* x      = (const float*)d_in[0];   // [4,2048,4096]
    const float* base_w = (const float*)d_in[1];   // [4096,4096]
    const float* base_b = (const float*)d_in[2];   // [4096]
    const float* lora_A = (const float*)d_in[3];   // [8,16,4096]
    const float* lora_B = (const float*)d_in[4];   // [8,4096,16]
    const float* rout_w = (const float*)d_in[5];   // [8,4096]
    const float* rout_b = (const float*)d_in[6];   // [8]
    float* out = (float*)d_out;

    const int SMEM_MAIN = 3 * (128 + 128) * 128;   // 98304 -> 2 CTA/SM
    const int SMEM_H    = 3 * (64 + 128) * 128;    // 73728
    cudaFuncSetAttribute(main_gemm_kernel,
                         cudaFuncAttributeMaxDynamicSharedMemorySize, SMEM_MAIN);
    cudaFuncSetAttribute(h_gemm_kernel,
                         cudaFuncAttributeMaxDynamicSharedMemorySize, SMEM_H);

    __half* xh;  cudaGetSymbolAddress((void**)&xh,  g_xh);
    __half* wh;  cudaGetSymbolAddress((void**)&wh,  g_wh);
    __half* ah;  cudaGetSymbolAddress((void**)&ah,  g_ah);
    __half* bwh; cudaGetSymbolAddress((void**)&bwh, g_Bwh);
    __half* hh;  cudaGetSymbolAddress((void**)&hh,  g_hh);
    float*  hp;  cudaGetSymbolAddress((void**)&hp,  g_hp);

    cvt_mean_kernel<<<dim3(D_DIM / 1024, B_DIM, NCHUNK), 256>>>(x, xh);
    cvt_f2h_kernel<<<((size_t)D_DIM * D_DIM) / 1024, 256>>>(base_w, wh);
    cvt_f2h_kernel<<<((size_t)KR * D_DIM) / 1024, 256>>>(lora_A, ah);

    router_a_kernel<<<dim3(B_DIM, 16), 256>>>(rout_w);
    bw_kernel<<<(B_DIM * D_DIM * KR) / 256, 256>>>(lora_B, rout_b);

    // h = x @ A_cat^T  split-K2 -> fp32 partials -> fp16
    h_gemm_kernel<<<dim3(1, T_TOK / 64, 2), 128, SMEM_H>>>(xh, ah, hp, 32);
    h_reduce_kernel<<<(T_TOK * KR / 2) / 256, 256>>>();

    // out = x @ W^T + h @ Bw^T + bias
    main_gemm_kernel<<<dim3(D_DIM / 128, T_TOK / 128), 128, SMEM_MAIN>>>(
        xh, wh, hh, bwh, base_b, out);
}

// round 11
// speedup vs baseline: 1.0106x; 1.0106x over previous
#include <cuda_runtime.h>
#include <cuda_fp16.h>
#include <cstdint>
#include <math.h>

// ---------------- Problem constants ----------------
#define D_DIM 4096
#define S_DIM 2048
#define B_DIM 4
#define K_EXP 8
#define R_DIM 16
#define KR    128
#define T_TOK 8192
#define SCALE 2.0f
#define NCHUNK 32          // mean-pool chunks (64 rows each)

// ---------------- Device scratch (static; no runtime alloc) ----------------
__device__ __align__(16) float  g_partial[B_DIM * NCHUNK * D_DIM];    // 2 MB
__device__ __align__(16) float  g_lp[B_DIM * 16 * K_EXP];             // partial logits
__device__ __align__(16) __half g_xh[(size_t)T_TOK * D_DIM];          // 64 MB
__device__ __align__(16) __half g_wh[(size_t)D_DIM * D_DIM];          // 32 MB
__device__ __align__(16) __half g_ah[(size_t)KR * D_DIM];             //  1 MB
__device__ __align__(16) __half g_Bwh[(size_t)B_DIM * D_DIM * KR];    //  4 MB
__device__ __align__(16) __half g_hh[(size_t)T_TOK * KR];             //  2 MB
__device__ __align__(16) float  g_hp[2][(size_t)T_TOK * KR];          //  8 MB

// ---------------- PTX helpers ----------------
__device__ __forceinline__ uint32_t smem_u32(const void* p) {
    uint32_t a;
    asm("{ .reg .u64 t; cvta.to.shared.u64 t, %1; cvt.u32.u64 %0, t; }"
        : "=r"(a) : "l"(p));
    return a;
}

#define CP_ASYNC16(dst, src) \
    asm volatile("cp.async.cg.shared.global [%0], [%1], 16;" \
                 :: "r"(dst), "l"(src) : "memory")
#define CP_COMMIT() asm volatile("cp.async.commit_group;" ::: "memory")
#define CP_WAIT(n)  asm volatile("cp.async.wait_group %0;" :: "n"(n) : "memory")

#define LDSM4(r0, r1, r2, r3, addr) \
    asm volatile("ldmatrix.sync.aligned.m8n8.x4.shared.b16 {%0,%1,%2,%3}, [%4];" \
                 : "=r"(r0), "=r"(r1), "=r"(r2), "=r"(r3) : "r"(addr))

#define MMA16816(d, a, b) \
    asm volatile("mma.sync.aligned.m16n8k16.row.col.f32.f16.f16.f32 " \
                 "{%0,%1,%2,%3},{%4,%5,%6,%7},{%8,%9},{%0,%1,%2,%3};" \
                 : "+f"((d)[0]), "+f"((d)[1]), "+f"((d)[2]), "+f"((d)[3]) \
                 : "r"((a)[0]), "r"((a)[1]), "r"((a)[2]), "r"((a)[3]), \
                   "r"((b)[0]), "r"((b)[1]))

// SW128 swizzle for 128-byte rows
__device__ __forceinline__ uint32_t sw128(uint32_t base, int row, int ch) {
    uint32_t off = (uint32_t)(row * 128 + ch * 16);
    return base + (off ^ ((off >> 3) & 0x70));
}

// ---------------------------------------------------------------------------
// Aux kernels
// ---------------------------------------------------------------------------
__global__ void cvt_f2h_kernel(const float* __restrict__ s, __half* __restrict__ d) {
    size_t i = ((size_t)blockIdx.x * 256 + threadIdx.x) * 4;
    float4 v = *(const float4*)(s + i);
    *(__half2*)(d + i)     = __floats2half2_rn(v.x, v.y);
    *(__half2*)(d + i + 2) = __floats2half2_rn(v.z, v.w);
}

// Fused x fp32->fp16 + column partial sums over 64-row chunks.
__global__ void cvt_mean_kernel(const float* __restrict__ x, __half* __restrict__ xh) {
    int d0 = blockIdx.x * 1024 + threadIdx.x * 4;
    int b  = blockIdx.y;
    int c  = blockIdx.z;
    size_t base = ((size_t)(b * S_DIM + c * 64)) * D_DIM + d0;
    float s0 = 0.f, s1 = 0.f, s2 = 0.f, s3 = 0.f;
#pragma unroll 8
    for (int i = 0; i < 64; i++) {
        float4 v = *(const float4*)(x + base + (size_t)i * D_DIM);
        s0 += v.x; s1 += v.y; s2 += v.z; s3 += v.w;
        *(__half2*)(xh + base + (size_t)i * D_DIM)     = __floats2half2_rn(v.x, v.y);
        *(__half2*)(xh + base + (size_t)i * D_DIM + 2) = __floats2half2_rn(v.z, v.w);
    }
    float4 s = { s0, s1, s2, s3 };
    *(float4*)(g_partial + (b * NCHUNK + c) * D_DIM + d0) = s;
}

// Router phase A: partial logits per (b, slice of 256 d-columns)
__global__ void router_a_kernel(const float* __restrict__ rw) {
    int b = blockIdx.x;
    int s = blockIdx.y;
    int tid = threadIdx.x;
    int d = s * 256 + tid;

    float m = 0.f;
#pragma unroll
    for (int c = 0; c < NCHUNK; c++) m += g_partial[(b * NCHUNK + c) * D_DIM + d];
    m *= (1.0f / (float)S_DIM);

    __shared__ float red[256];
#pragma unroll
    for (int k = 0; k < K_EXP; k++) {
        red[tid] = m * rw[k * D_DIM + d];
        __syncthreads();
#pragma unroll
        for (int off = 128; off > 0; off >>= 1) {
            if (tid < off) red[tid] += red[tid + off];
            __syncthreads();
        }
        if (tid == 0) g_lp[(b * 16 + s) * K_EXP + k] = red[0];
        __syncthreads();
    }
}

// bw_kernel with fused softmax: each block recomputes the 4x8 router softmax
// from g_lp (8-lane shfl groups), then scales lora_B.
__global__ void bw_kernel(const float* __restrict__ loraB, const float* __restrict__ rb) {
    __shared__ float w[B_DIM * K_EXP];
    if (threadIdx.x < 32) {
        int t = threadIdx.x;
        int b = t >> 3, k = t & 7;
        float s = 0.f;
#pragma unroll
        for (int q = 0; q < 16; q++) s += g_lp[(b * 16 + q) * K_EXP + k];
        s += rb[k];
        float mx = s;
#pragma unroll
        for (int off = 4; off > 0; off >>= 1)
            mx = fmaxf(mx, __shfl_xor_sync(0xffffffffu, mx, off));
        float e = expf(s - mx);
        float sum = e;
#pragma unroll
        for (int off = 4; off > 0; off >>= 1)
            sum += __shfl_xor_sync(0xffffffffu, sum, off);
        w[t] = e / sum;
    }
    __syncthreads();

    int idx = blockIdx.x * 256 + threadIdx.x;           // < 2^21
    int b   = idx >> 19;
    int rem = idx & ((1 << 19) - 1);
    int o   = rem >> 7;
    int c   = rem & 127;
    int k   = c >> 4;
    int r   = c & 15;
    float v = SCALE * w[b * K_EXP + k] * loraB[(k * D_DIM + o) * R_DIM + r];
    g_Bwh[idx] = __float2half_rn(v);
}

__global__ void h_reduce_kernel() {
    size_t i = (size_t)blockIdx.x * 256 + threadIdx.x;
    float2 a = *(const float2*)(g_hp[0] + 2 * i);
    float2 b = *(const float2*)(g_hp[1] + 2 * i);
    *(__half2*)(g_hh + 2 * i) = __floats2half2_rn(a.x + b.x, a.y + b.y);
}

// ---------------------------------------------------------------------------
// h-GEMM: warp tile 64x32, BK=64, 3-stage, split-K z (R8 config, validated).
// ---------------------------------------------------------------------------
__global__ void __launch_bounds__(128, 2) h_gemm_kernel(
    const __half* __restrict__ A, const __half* __restrict__ Bm,
    float* __restrict__ outf, int iters)
{
    constexpr int BM = 64, BN = 128;
    constexpr int THREADS = 128;
    constexpr int ABYT = BM * 128;
    constexpr int STG  = (BM + BN) * 128;

    extern __shared__ __align__(128) char smem[];
    const uint32_t sbase = smem_u32(smem);
    const int tid  = threadIdx.x;
    const int lane = tid & 31;
    const int wid  = tid >> 5;
    const int wn   = wid;                  // 4 warps over N
    const int i0   = blockIdx.y * BM;
    const int zo   = blockIdx.z * iters * 64;
    A  += zo;
    Bm += zo;
    outf += (size_t)blockIdx.z * ((size_t)T_TOK * KR);

    auto loadst = [&](int git, int st) {
        uint32_t abase = sbase + st * STG;
        uint32_t bbase = abase + ABYT;
        int koff = git * 64;
#pragma unroll
        for (int t = 0; t < (BM * 8) / THREADS; t++) {
            int idx = tid + t * THREADS;
            int row = idx >> 3, ch = idx & 7;
            CP_ASYNC16(sw128(abase, row, ch),
                       A + (size_t)(i0 + row) * D_DIM + koff + ch * 8);
        }
#pragma unroll
        for (int t = 0; t < (BN * 8) / THREADS; t++) {
            int idx = tid + t * THREADS;
            int row = idx >> 3, ch = idx & 7;
            CP_ASYNC16(sw128(bbase, row, ch),
                       Bm + (size_t)row * D_DIM + koff + ch * 8);
        }
    };

    float acc[4][4][4];
#pragma unroll
    for (int mi = 0; mi < 4; mi++)
#pragma unroll
        for (int ni = 0; ni < 4; ni++)
#pragma unroll
            for (int e = 0; e < 4; e++) acc[mi][ni][e] = 0.f;

    loadst(0, 0); CP_COMMIT();
    loadst(1, 1); CP_COMMIT();

    int st = 0, pf = 2;
    for (int it = 0; it < iters; ++it) {
        CP_WAIT(1);
        __syncthreads();
        if (it + 2 < iters) loadst(it + 2, pf);
        CP_COMMIT();

        uint32_t sA = sbase + st * STG;
        uint32_t sB = sA + ABYT;
#pragma unroll
        for (int ks = 0; ks < 4; ks++) {
            int ch = ks * 2 + (lane >> 4);
            uint32_t a[4][4];
#pragma unroll
            for (int mi = 0; mi < 4; mi++) {
                int row = mi * 16 + (lane & 15);
                LDSM4(a[mi][0], a[mi][1], a[mi][2], a[mi][3], sw128(sA, row, ch));
            }
            uint32_t b[4][2];
#pragma unroll
            for (int j = 0; j < 2; j++) {
                int row = wn * 32 + j * 16 + (lane & 15);
                uint32_t t0, t1, t2, t3;
                LDSM4(t0, t1, t2, t3, sw128(sB, row, ch));
                b[2 * j][0]     = t0; b[2 * j][1]     = t2;
                b[2 * j + 1][0] = t1; b[2 * j + 1][1] = t3;
            }
#pragma unroll
            for (int mi = 0; mi < 4; mi++)
#pragma unroll
                for (int ni = 0; ni < 4; ni++)
                    MMA16816(acc[mi][ni], a[mi], b[ni]);
        }
        st = (st == 2) ? 0 : st + 1;
        pf = (pf == 2) ? 0 : pf + 1;
    }

#pragma unroll
    for (int mi = 0; mi < 4; mi++) {
        int r0 = i0 + mi * 16 + (lane >> 2);
#pragma unroll
        for (int ni = 0; ni < 4; ni++) {
            int c0 = wn * 32 + ni * 8 + 2 * (lane & 3);
            float2 v0 = { acc[mi][ni][0], acc[mi][ni][1] };
            float2 v1 = { acc[mi][ni][2], acc[mi][ni][3] };
            *(float2*)(outf + (size_t)r0 * KR + c0)       = v0;
            *(float2*)(outf + (size_t)(r0 + 8) * KR + c0) = v1;
        }
    }
}

// ---------------------------------------------------------------------------
// Main GEMM: BM=128, BN=128, BK=64, 4 warps (2x2 of 64x64), 128 threads,
// 3-stage ring (96 KB) -> 2 CTA/SM. R8 mainloop; loader base/ld hoisted.
//   out = x@W^T (64 iters) + h@Bw^T (2 iters) + bias
// ---------------------------------------------------------------------------
__global__ void __launch_bounds__(128, 2) main_gemm_kernel(
    const __half* __restrict__ A,
    const __half* __restrict__ Bm,
    const __half* __restrict__ A2,
    const __half* __restrict__ B2all,
    const float* __restrict__ bias,
    float* __restrict__ outf)
{
    constexpr int BM = 128, BN = 128, THREADS = 128;
    constexpr int ITER0 = 64, ITERS = 66;
    constexpr int ABYT = BM * 128;           // 16 KB
    constexpr int STG  = (BM + BN) * 128;    // 32 KB

    extern __shared__ __align__(128) char smem[];
    const uint32_t sbase = smem_u32(smem);
    const int tid  = threadIdx.x;
    const int lane = tid & 31;
    const int wid  = tid >> 5;
    const int wm   = wid & 1;       // 2 warps over M (64 each)
    const int wn   = wid >> 1;      // 2 warps over N (64 each)
    const int i0   = blockIdx.y * BM;
    const int j0   = blockIdx.x * BN;
    const __half* B2 = B2all + (size_t)(i0 >> 11) * ((size_t)D_DIM * KR);

    auto loadst = [&](int git, int st) {
        uint32_t abase = sbase + st * STG;
        uint32_t bbase = abase + ABYT;
        // hoisted source select: one branch per call, pure IMAD inside
        const __half* Asrc;
        const __half* Bsrc;
        size_t ld;
        if (git < ITER0) {
            Asrc = A  + (size_t)i0 * D_DIM + git * 64;
            Bsrc = Bm + (size_t)j0 * D_DIM + git * 64;
            ld = D_DIM;
        } else {
            Asrc = A2 + (size_t)i0 * KR + (git - ITER0) * 64;
            Bsrc = B2 + (size_t)j0 * KR + (git - ITER0) * 64;
            ld = KR;
        }
#pragma unroll
        for (int t = 0; t < (BM * 8) / THREADS; t++) {
            int idx = tid + t * THREADS;
            int row = idx >> 3, ch = idx & 7;
            CP_ASYNC16(sw128(abase, row, ch), Asrc + (size_t)row * ld + ch * 8);
        }
#pragma unroll
        for (int t = 0; t < (BN * 8) / THREADS; t++) {
            int idx = tid + t * THREADS;
            int row = idx >> 3, ch = idx & 7;
            CP_ASYNC16(sw128(bbase, row, ch), Bsrc + (size_t)row * ld + ch * 8);
        }
    };

    float acc[4][8][4];
#pragma unroll
    for (int mi = 0; mi < 4; mi++)
#pragma unroll
        for (int ni = 0; ni < 8; ni++)
#pragma unroll
            for (int e = 0; e < 4; e++) acc[mi][ni][e] = 0.f;

    loadst(0, 0); CP_COMMIT();
    loadst(1, 1); CP_COMMIT();

    int st = 0, pf = 2;
    for (int it = 0; it < ITERS; ++it) {
        CP_WAIT(1);
        __syncthreads();
        if (it + 2 < ITERS) loadst(it + 2, pf);
        CP_COMMIT();

        uint32_t sA = sbase + st * STG;
        uint32_t sB = sA + ABYT;
#pragma unroll
        for (int ks = 0; ks < 4; ks++) {
            int ch = ks * 2 + (lane >> 4);
            uint32_t a[4][4];
#pragma unroll
            for (int mi = 0; mi < 4; mi++) {
                int row = wm * 64 + mi * 16 + (lane & 15);
                LDSM4(a[mi][0], a[mi][1], a[mi][2], a[mi][3], sw128(sA, row, ch));
            }
            uint32_t b[8][2];
#pragma unroll
            for (int j = 0; j < 4; j++) {
                int row = wn * 64 + j * 16 + (lane & 15);
                uint32_t t0, t1, t2, t3;
                LDSM4(t0, t1, t2, t3, sw128(sB, row, ch));
                b[2 * j][0]     = t0; b[2 * j][1]     = t2;
                b[2 * j + 1][0] = t1; b[2 * j + 1][1] = t3;
            }
#pragma unroll
            for (int mi = 0; mi < 4; mi++)
#pragma unroll
                for (int ni = 0; ni < 8; ni++)
                    MMA16816(acc[mi][ni], a[mi], b[ni]);
        }
        st = (st == 2) ? 0 : st + 1;
        pf = (pf == 2) ? 0 : pf + 1;
    }

    // epilogue: bias + write
#pragma unroll
    for (int mi = 0; mi < 4; mi++) {
        int r0 = i0 + wm * 64 + mi * 16 + (lane >> 2);
#pragma unroll
        for (int ni = 0; ni < 8; ni++) {
            int c0 = j0 + wn * 64 + ni * 8 + 2 * (lane & 3);
            float b0 = bias[c0], b1 = bias[c0 + 1];
            float2 v0 = { acc[mi][ni][0] + b0, acc[mi][ni][1] + b1 };
            float2 v1 = { acc[mi][ni][2] + b0, acc[mi][ni][3] + b1 };
            *(float2*)(outf + (size_t)r0 * D_DIM + c0)       = v0;
            *(float2*)(outf + (size_t)(r0 + 8) * D_DIM + c0) = v1;
        }
    }
}

// ---------------------------------------------------------------------------
extern "C" void kernel_launch(void* const* d_in, const int* in_sizes, int n_in,
                              void* d_out, int out_size) {
    const float* x      = (const float*)d_in[0];   // [4,2048,4096]
    const float* base_w = (const float*)d_in[1];   // [4096,4096]
    const float* base_b = (const float*)d_in[2];   // [4096]
    const float* lora_A = (const float*)d_in[3];   // [8,16,4096]
    const float* lora_B = (const float*)d_in[4];   // [8,4096,16]
    const float* rout_w = (const float*)d_in[5];   // [8,4096]
    const float* rout_b = (const float*)d_in[6];   // [8]
    float* out = (float*)d_out;

    const int SMEM_MAIN = 3 * (128 + 128) * 128;   // 98304 -> 2 CTA/SM
    const int SMEM_H    = 3 * (64 + 128) * 128;    // 73728
    cudaFuncSetAttribute(main_gemm_kernel,
                         cudaFuncAttributeMaxDynamicSharedMemorySize, SMEM_MAIN);
    cudaFuncSetAttribute(h_gemm_kernel,
                         cudaFuncAttributeMaxDynamicSharedMemorySize, SMEM_H);

    __half* xh;  cudaGetSymbolAddress((void**)&xh,  g_xh);
    __half* wh;  cudaGetSymbolAddress((void**)&wh,  g_wh);
    __half* ah;  cudaGetSymbolAddress((void**)&ah,  g_ah);
    __half* bwh; cudaGetSymbolAddress((void**)&bwh, g_Bwh);
    __half* hh;  cudaGetSymbolAddress((void**)&hh,  g_hh);
    float*  hp;  cudaGetSymbolAddress((void**)&hp,  g_hp);

    cvt_mean_kernel<<<dim3(D_DIM / 1024, B_DIM, NCHUNK), 256>>>(x, xh);
    cvt_f2h_kernel<<<((size_t)D_DIM * D_DIM) / 1024, 256>>>(base_w, wh);
    cvt_f2h_kernel<<<((size_t)KR * D_DIM) / 1024, 256>>>(lora_A, ah);

    router_a_kernel<<<dim3(B_DIM, 16), 256>>>(rout_w);
    bw_kernel<<<(B_DIM * D_DIM * KR) / 256, 256>>>(lora_B, rout_b);

    // h = x @ A_cat^T  split-K2 -> fp32 partials -> fp16
    h_gemm_kernel<<<dim3(1, T_TOK / 64, 2), 128, SMEM_H>>>(xh, ah, hp, 32);
    h_reduce_kernel<<<(T_TOK * KR / 2) / 256, 256>>>();

    // out = x @ W^T + h @ Bw^T + bias
    main_gemm_kernel<<<dim3(D_DIM / 128, T_TOK / 128), 128, SMEM_MAIN>>>(
        xh, wh, hh, bwh, base_b, out);
}

// round 12
// speedup vs baseline: 1.0132x; 1.0025x over previous
#include <cuda_runtime.h>
#include <cuda_fp16.h>
#include <cstdint>
#include <math.h>

// ---------------- Problem constants ----------------
#define D_DIM 4096
#define S_DIM 2048
#define B_DIM 4
#define K_EXP 8
#define R_DIM 16
#define KR    128
#define T_TOK 8192
#define SCALE 2.0f
#define NCHUNK 32          // mean-pool chunks (64 rows each)

// ---------------- Device scratch (static; no runtime alloc) ----------------
__device__ __align__(16) float  g_partial[B_DIM * NCHUNK * D_DIM];    // 2 MB
__device__ __align__(16) float  g_lp[B_DIM * 16 * K_EXP];             // partial logits
__device__ __align__(16) __half g_xh[(size_t)T_TOK * D_DIM];          // 64 MB
__device__ __align__(16) __half g_wh[(size_t)D_DIM * D_DIM];          // 32 MB
__device__ __align__(16) __half g_ah[(size_t)KR * D_DIM];             //  1 MB
__device__ __align__(16) __half g_Bwh[(size_t)B_DIM * D_DIM * KR];    //  4 MB
__device__ __align__(16) __half g_hh[(size_t)T_TOK * KR];             //  2 MB
__device__ __align__(16) float  g_hp[2][(size_t)T_TOK * KR];          //  8 MB

// ---------------- PTX helpers ----------------
__device__ __forceinline__ uint32_t smem_u32(const void* p) {
    uint32_t a;
    asm("{ .reg .u64 t; cvta.to.shared.u64 t, %1; cvt.u32.u64 %0, t; }"
        : "=r"(a) : "l"(p));
    return a;
}

#define CP_ASYNC16(dst, src) \
    asm volatile("cp.async.cg.shared.global [%0], [%1], 16;" \
                 :: "r"(dst), "l"(src) : "memory")
#define CP_COMMIT() asm volatile("cp.async.commit_group;" ::: "memory")
#define CP_WAIT(n)  asm volatile("cp.async.wait_group %0;" :: "n"(n) : "memory")

#define LDSM4(r0, r1, r2, r3, addr) \
    asm volatile("ldmatrix.sync.aligned.m8n8.x4.shared.b16 {%0,%1,%2,%3}, [%4];" \
                 : "=r"(r0), "=r"(r1), "=r"(r2), "=r"(r3) : "r"(addr))

#define MMA16816(d, a, b) \
    asm volatile("mma.sync.aligned.m16n8k16.row.col.f32.f16.f16.f32 " \
                 "{%0,%1,%2,%3},{%4,%5,%6,%7},{%8,%9},{%0,%1,%2,%3};" \
                 : "+f"((d)[0]), "+f"((d)[1]), "+f"((d)[2]), "+f"((d)[3]) \
                 : "r"((a)[0]), "r"((a)[1]), "r"((a)[2]), "r"((a)[3]), \
                   "r"((b)[0]), "r"((b)[1]))

// SW128 swizzle for 128-byte rows
__device__ __forceinline__ uint32_t sw128(uint32_t base, int row, int ch) {
    uint32_t off = (uint32_t)(row * 128 + ch * 16);
    return base + (off ^ ((off >> 3) & 0x70));
}

// ---------------------------------------------------------------------------
// Aux kernels (identical to R11)
// ---------------------------------------------------------------------------
__global__ void cvt_f2h_kernel(const float* __restrict__ s, __half* __restrict__ d) {
    size_t i = ((size_t)blockIdx.x * 256 + threadIdx.x) * 4;
    float4 v = *(const float4*)(s + i);
    *(__half2*)(d + i)     = __floats2half2_rn(v.x, v.y);
    *(__half2*)(d + i + 2) = __floats2half2_rn(v.z, v.w);
}

__global__ void cvt_mean_kernel(const float* __restrict__ x, __half* __restrict__ xh) {
    int d0 = blockIdx.x * 1024 + threadIdx.x * 4;
    int b  = blockIdx.y;
    int c  = blockIdx.z;
    size_t base = ((size_t)(b * S_DIM + c * 64)) * D_DIM + d0;
    float s0 = 0.f, s1 = 0.f, s2 = 0.f, s3 = 0.f;
#pragma unroll 8
    for (int i = 0; i < 64; i++) {
        float4 v = *(const float4*)(x + base + (size_t)i * D_DIM);
        s0 += v.x; s1 += v.y; s2 += v.z; s3 += v.w;
        *(__half2*)(xh + base + (size_t)i * D_DIM)     = __floats2half2_rn(v.x, v.y);
        *(__half2*)(xh + base + (size_t)i * D_DIM + 2) = __floats2half2_rn(v.z, v.w);
    }
    float4 s = { s0, s1, s2, s3 };
    *(float4*)(g_partial + (b * NCHUNK + c) * D_DIM + d0) = s;
}

__global__ void router_a_kernel(const float* __restrict__ rw) {
    int b = blockIdx.x;
    int s = blockIdx.y;
    int tid = threadIdx.x;
    int d = s * 256 + tid;

    float m = 0.f;
#pragma unroll
    for (int c = 0; c < NCHUNK; c++) m += g_partial[(b * NCHUNK + c) * D_DIM + d];
    m *= (1.0f / (float)S_DIM);

    __shared__ float red[256];
#pragma unroll
    for (int k = 0; k < K_EXP; k++) {
        red[tid] = m * rw[k * D_DIM + d];
        __syncthreads();
#pragma unroll
        for (int off = 128; off > 0; off >>= 1) {
            if (tid < off) red[tid] += red[tid + off];
            __syncthreads();
        }
        if (tid == 0) g_lp[(b * 16 + s) * K_EXP + k] = red[0];
        __syncthreads();
    }
}

__global__ void bw_kernel(const float* __restrict__ loraB, const float* __restrict__ rb) {
    __shared__ float w[B_DIM * K_EXP];
    if (threadIdx.x < 32) {
        int t = threadIdx.x;
        int b = t >> 3, k = t & 7;
        float s = 0.f;
#pragma unroll
        for (int q = 0; q < 16; q++) s += g_lp[(b * 16 + q) * K_EXP + k];
        s += rb[k];
        float mx = s;
#pragma unroll
        for (int off = 4; off > 0; off >>= 1)
            mx = fmaxf(mx, __shfl_xor_sync(0xffffffffu, mx, off));
        float e = expf(s - mx);
        float sum = e;
#pragma unroll
        for (int off = 4; off > 0; off >>= 1)
            sum += __shfl_xor_sync(0xffffffffu, sum, off);
        w[t] = e / sum;
    }
    __syncthreads();

    int idx = blockIdx.x * 256 + threadIdx.x;           // < 2^21
    int b   = idx >> 19;
    int rem = idx & ((1 << 19) - 1);
    int o   = rem >> 7;
    int c   = rem & 127;
    int k   = c >> 4;
    int r   = c & 15;
    float v = SCALE * w[b * K_EXP + k] * loraB[(k * D_DIM + o) * R_DIM + r];
    g_Bwh[idx] = __float2half_rn(v);
}

__global__ void h_reduce_kernel() {
    size_t i = (size_t)blockIdx.x * 256 + threadIdx.x;
    float2 a = *(const float2*)(g_hp[0] + 2 * i);
    float2 b = *(const float2*)(g_hp[1] + 2 * i);
    *(__half2*)(g_hh + 2 * i) = __floats2half2_rn(a.x + b.x, a.y + b.y);
}

// ---------------------------------------------------------------------------
// h-GEMM: warp tile 64x32, BK=64, 3-stage, split-K z (validated).
// ---------------------------------------------------------------------------
__global__ void __launch_bounds__(128, 2) h_gemm_kernel(
    const __half* __restrict__ A, const __half* __restrict__ Bm,
    float* __restrict__ outf, int iters)
{
    constexpr int BM = 64, BN = 128;
    constexpr int THREADS = 128;
    constexpr int ABYT = BM * 128;
    constexpr int STG  = (BM + BN) * 128;

    extern __shared__ __align__(128) char smem[];
    const uint32_t sbase = smem_u32(smem);
    const int tid  = threadIdx.x;
    const int lane = tid & 31;
    const int wid  = tid >> 5;
    const int wn   = wid;                  // 4 warps over N
    const int i0   = blockIdx.y * BM;
    const int zo   = blockIdx.z * iters * 64;
    A  += zo;
    Bm += zo;
    outf += (size_t)blockIdx.z * ((size_t)T_TOK * KR);

    auto loadst = [&](int git, int st) {
        uint32_t abase = sbase + st * STG;
        uint32_t bbase = abase + ABYT;
        int koff = git * 64;
#pragma unroll
        for (int t = 0; t < (BM * 8) / THREADS; t++) {
            int idx = tid + t * THREADS;
            int row = idx >> 3, ch = idx & 7;
            CP_ASYNC16(sw128(abase, row, ch),
                       A + (size_t)(i0 + row) * D_DIM + koff + ch * 8);
        }
#pragma unroll
        for (int t = 0; t < (BN * 8) / THREADS; t++) {
            int idx = tid + t * THREADS;
            int row = idx >> 3, ch = idx & 7;
            CP_ASYNC16(sw128(bbase, row, ch),
                       Bm + (size_t)row * D_DIM + koff + ch * 8);
        }
    };

    float acc[4][4][4];
#pragma unroll
    for (int mi = 0; mi < 4; mi++)
#pragma unroll
        for (int ni = 0; ni < 4; ni++)
#pragma unroll
            for (int e = 0; e < 4; e++) acc[mi][ni][e] = 0.f;

    loadst(0, 0); CP_COMMIT();
    loadst(1, 1); CP_COMMIT();

    int st = 0, pf = 2;
    for (int it = 0; it < iters; ++it) {
        CP_WAIT(1);
        __syncthreads();
        if (it + 2 < iters) loadst(it + 2, pf);
        CP_COMMIT();

        uint32_t sA = sbase + st * STG;
        uint32_t sB = sA + ABYT;
#pragma unroll
        for (int ks = 0; ks < 4; ks++) {
            int ch = ks * 2 + (lane >> 4);
            uint32_t a[4][4];
#pragma unroll
            for (int mi = 0; mi < 4; mi++) {
                int row = mi * 16 + (lane & 15);
                LDSM4(a[mi][0], a[mi][1], a[mi][2], a[mi][3], sw128(sA, row, ch));
            }
            uint32_t b[4][2];
#pragma unroll
            for (int j = 0; j < 2; j++) {
                int row = wn * 32 + j * 16 + (lane & 15);
                uint32_t t0, t1, t2, t3;
                LDSM4(t0, t1, t2, t3, sw128(sB, row, ch));
                b[2 * j][0]     = t0; b[2 * j][1]     = t2;
                b[2 * j + 1][0] = t1; b[2 * j + 1][1] = t3;
            }
#pragma unroll
            for (int mi = 0; mi < 4; mi++)
#pragma unroll
                for (int ni = 0; ni < 4; ni++)
                    MMA16816(acc[mi][ni], a[mi], b[ni]);
        }
        st = (st == 2) ? 0 : st + 1;
        pf = (pf == 2) ? 0 : pf + 1;
    }

#pragma unroll
    for (int mi = 0; mi < 4; mi++) {
        int r0 = i0 + mi * 16 + (lane >> 2);
#pragma unroll
        for (int ni = 0; ni < 4; ni++) {
            int c0 = wn * 32 + ni * 8 + 2 * (lane & 3);
            float2 v0 = { acc[mi][ni][0], acc[mi][ni][1] };
            float2 v1 = { acc[mi][ni][2], acc[mi][ni][3] };
            *(float2*)(outf + (size_t)r0 * KR + c0)       = v0;
            *(float2*)(outf + (size_t)(r0 + 8) * KR + c0) = v1;
        }
    }
}

// ---------------------------------------------------------------------------
// Main GEMM: BM=128, BN=128, BK=64, 4 warps (2x2 of 64x64), 128 threads,
// 3-stage ring (96 KB) -> 2 CTA/SM (R8/R11 mainloop).
// ---------------------------------------------------------------------------
__global__ void __launch_bounds__(128, 2) main_gemm_kernel(
    const __half* __restrict__ A,
    const __half* __restrict__ Bm,
    const __half* __restrict__ A2,
    const __half* __restrict__ B2all,
    const float* __restrict__ bias,
    float* __restrict__ outf)
{
    constexpr int BM = 128, BN = 128, THREADS = 128;
    constexpr int ITER0 = 64, ITERS = 66;
    constexpr int ABYT = BM * 128;           // 16 KB
    constexpr int STG  = (BM + BN) * 128;    // 32 KB

    extern __shared__ __align__(128) char smem[];
    const uint32_t sbase = smem_u32(smem);
    const int tid  = threadIdx.x;
    const int lane = tid & 31;
    const int wid  = tid >> 5;
    const int wm   = wid & 1;
    const int wn   = wid >> 1;
    const int i0   = blockIdx.y * BM;
    const int j0   = blockIdx.x * BN;
    const __half* B2 = B2all + (size_t)(i0 >> 11) * ((size_t)D_DIM * KR);

    auto loadst = [&](int git, int st) {
        uint32_t abase = sbase + st * STG;
        uint32_t bbase = abase + ABYT;
        const __half* Asrc;
        const __half* Bsrc;
        size_t ld;
        if (git < ITER0) {
            Asrc = A  + (size_t)i0 * D_DIM + git * 64;
            Bsrc = Bm + (size_t)j0 * D_DIM + git * 64;
            ld = D_DIM;
        } else {
            Asrc = A2 + (size_t)i0 * KR + (git - ITER0) * 64;
            Bsrc = B2 + (size_t)j0 * KR + (git - ITER0) * 64;
            ld = KR;
        }
#pragma unroll
        for (int t = 0; t < (BM * 8) / THREADS; t++) {
            int idx = tid + t * THREADS;
            int row = idx >> 3, ch = idx & 7;
            CP_ASYNC16(sw128(abase, row, ch), Asrc + (size_t)row * ld + ch * 8);
        }
#pragma unroll
        for (int t = 0; t < (BN * 8) / THREADS; t++) {
            int idx = tid + t * THREADS;
            int row = idx >> 3, ch = idx & 7;
            CP_ASYNC16(sw128(bbase, row, ch), Bsrc + (size_t)row * ld + ch * 8);
        }
    };

    float acc[4][8][4];
#pragma unroll
    for (int mi = 0; mi < 4; mi++)
#pragma unroll
        for (int ni = 0; ni < 8; ni++)
#pragma unroll
            for (int e = 0; e < 4; e++) acc[mi][ni][e] = 0.f;

    loadst(0, 0); CP_COMMIT();
    loadst(1, 1); CP_COMMIT();

    int st = 0, pf = 2;
    for (int it = 0; it < ITERS; ++it) {
        CP_WAIT(1);
        __syncthreads();
        if (it + 2 < ITERS) loadst(it + 2, pf);
        CP_COMMIT();

        uint32_t sA = sbase + st * STG;
        uint32_t sB = sA + ABYT;
#pragma unroll
        for (int ks = 0; ks < 4; ks++) {
            int ch = ks * 2 + (lane >> 4);
            uint32_t a[4][4];
#pragma unroll
            for (int mi = 0; mi < 4; mi++) {
                int row = wm * 64 + mi * 16 + (lane & 15);
                LDSM4(a[mi][0], a[mi][1], a[mi][2], a[mi][3], sw128(sA, row, ch));
            }
            uint32_t b[8][2];
#pragma unroll
            for (int j = 0; j < 4; j++) {
                int row = wn * 64 + j * 16 + (lane & 15);
                uint32_t t0, t1, t2, t3;
                LDSM4(t0, t1, t2, t3, sw128(sB, row, ch));
                b[2 * j][0]     = t0; b[2 * j][1]     = t2;
                b[2 * j + 1][0] = t1; b[2 * j + 1][1] = t3;
            }
#pragma unroll
            for (int mi = 0; mi < 4; mi++)
#pragma unroll
                for (int ni = 0; ni < 8; ni++)
                    MMA16816(acc[mi][ni], a[mi], b[ni]);
        }
        st = (st == 2) ? 0 : st + 1;
        pf = (pf == 2) ? 0 : pf + 1;
    }

#pragma unroll
    for (int mi = 0; mi < 4; mi++) {
        int r0 = i0 + wm * 64 + mi * 16 + (lane >> 2);
#pragma unroll
        for (int ni = 0; ni < 8; ni++) {
            int c0 = j0 + wn * 64 + ni * 8 + 2 * (lane & 3);
            float b0 = bias[c0], b1 = bias[c0 + 1];
            float2 v0 = { acc[mi][ni][0] + b0, acc[mi][ni][1] + b1 };
            float2 v1 = { acc[mi][ni][2] + b0, acc[mi][ni][3] + b1 };
            *(float2*)(outf + (size_t)r0 * D_DIM + c0)       = v0;
            *(float2*)(outf + (size_t)(r0 + 8) * D_DIM + c0) = v1;
        }
    }
}

// ---------------------------------------------------------------------------
// Host: lazily-created side streams + events (host resources only; device
// work per call is identical and deterministic). Never destroyed, so an
// in-flight graph capture is never invalidated.
// ---------------------------------------------------------------------------
static cudaStream_t g_s1 = nullptr;
static cudaStream_t g_s2 = nullptr;
static cudaEvent_t  g_e0, g_e1, g_em, g_e2;
static bool         g_streams_ok = false;

extern "C" void kernel_launch(void* const* d_in, const int* in_sizes, int n_in,
                              void* d_out, int out_size) {
    const float* x      = (const float*)d_in[0];   // [4,2048,4096]
    const float* base_w = (const float*)d_in[1];   // [4096,4096]
    const float* base_b = (const float*)d_in[2];   // [4096]
    const float* lora_A = (const float*)d_in[3];   // [8,16,4096]
    const float* lora_B = (const float*)d_in[4];   // [8,4096,16]
    const float* rout_w = (const float*)d_in[5];   // [8,4096]
    const float* rout_b = (const float*)d_in[6];   // [8]
    float* out = (float*)d_out;

    if (g_s1 == nullptr) {
        bool ok = true;
        ok &= (cudaStreamCreateWithFlags(&g_s1, cudaStreamNonBlocking) == cudaSuccess);
        ok &= (cudaStreamCreateWithFlags(&g_s2, cudaStreamNonBlocking) == cudaSuccess);
        ok &= (cudaEventCreateWithFlags(&g_e0, cudaEventDisableTiming) == cudaSuccess);
        ok &= (cudaEventCreateWithFlags(&g_e1, cudaEventDisableTiming) == cudaSuccess);
        ok &= (cudaEventCreateWithFlags(&g_em, cudaEventDisableTiming) == cudaSuccess);
        ok &= (cudaEventCreateWithFlags(&g_e2, cudaEventDisableTiming) == cudaSuccess);
        g_streams_ok = ok;
    }

    const int SMEM_MAIN = 3 * (128 + 128) * 128;   // 98304 -> 2 CTA/SM
    const int SMEM_H    = 3 * (64 + 128) * 128;    // 73728
    cudaFuncSetAttribute(main_gemm_kernel,
                         cudaFuncAttributeMaxDynamicSharedMemorySize, SMEM_MAIN);
    cudaFuncSetAttribute(h_gemm_kernel,
                         cudaFuncAttributeMaxDynamicSharedMemorySize, SMEM_H);

    __half* xh;  cudaGetSymbolAddress((void**)&xh,  g_xh);
    __half* wh;  cudaGetSymbolAddress((void**)&wh,  g_wh);
    __half* ah;  cudaGetSymbolAddress((void**)&ah,  g_ah);
    __half* bwh; cudaGetSymbolAddress((void**)&bwh, g_Bwh);
    __half* hh;  cudaGetSymbolAddress((void**)&hh,  g_hh);
    float*  hp;  cudaGetSymbolAddress((void**)&hp,  g_hp);

    cudaStream_t s0 = (cudaStream_t)0;
    cudaStream_t sW = g_streams_ok ? g_s1 : s0;   // W convert (independent)
    cudaStream_t sR = g_streams_ok ? g_s2 : s0;   // router chain (after cvt_mean)

    if (g_streams_ok) {
        // fork point: side streams join capture via event from stream 0
        cudaEventRecord(g_e0, s0);
        cudaStreamWaitEvent(sW, g_e0, 0);
    }

    // sW: W fp32 -> fp16 (no dependencies)
    cvt_f2h_kernel<<<((size_t)D_DIM * D_DIM) / 1024, 256, 0, sW>>>(base_w, wh);
    if (g_streams_ok) cudaEventRecord(g_e1, sW);

    // s0: x convert + mean partials (critical path)
    cvt_mean_kernel<<<dim3(D_DIM / 1024, B_DIM, NCHUNK), 256, 0, s0>>>(x, xh);

    if (g_streams_ok) {
        cudaEventRecord(g_em, s0);
        cudaStreamWaitEvent(sR, g_em, 0);
    }
    // sR: router logits + fused softmax + Bw build (needs g_partial only)
    router_a_kernel<<<dim3(B_DIM, 16), 256, 0, sR>>>(rout_w);
    bw_kernel<<<(B_DIM * D_DIM * KR) / 256, 256, 0, sR>>>(lora_B, rout_b);
    if (g_streams_ok) cudaEventRecord(g_e2, sR);

    // s0: lora_A convert + h = x @ A_cat^T (split-K2) + reduce
    cvt_f2h_kernel<<<((size_t)KR * D_DIM) / 1024, 256, 0, s0>>>(lora_A, ah);
    h_gemm_kernel<<<dim3(1, T_TOK / 64, 2), 128, SMEM_H, s0>>>(xh, ah, hp, 32);
    h_reduce_kernel<<<(T_TOK * KR / 2) / 256, 256, 0, s0>>>();

    if (g_streams_ok) {
        // join: main needs wh (sW) and bwh (sR)
        cudaStreamWaitEvent(s0, g_e1, 0);
        cudaStreamWaitEvent(s0, g_e2, 0);
    }

    // out = x @ W^T + h @ Bw^T + bias
    main_gemm_kernel<<<dim3(D_DIM / 128, T_TOK / 128), 128, SMEM_MAIN, s0>>>(
        xh, wh, hh, bwh, base_b, out);
}

// round 13
// speedup vs baseline: 1.0230x; 1.0097x over previous
#include <cuda_runtime.h>
#include <cuda_fp16.h>
#include <cstdint>
#include <math.h>

// ---------------- Problem constants ----------------
#define D_DIM 4096
#define S_DIM 2048
#define B_DIM 4
#define K_EXP 8
#define R_DIM 16
#define KR    128
#define T_TOK 8192
#define SCALE 2.0f
#define NCHUNK 64          // mean-pool chunks (32 rows each)
#define HSPLIT 4           // split-K planes for h-GEMM

// ---------------- Device scratch (static; no runtime alloc) ----------------
__device__ __align__(16) float  g_partial[B_DIM * NCHUNK * D_DIM];    // 4 MB
__device__ __align__(16) float  g_lp[B_DIM * 16 * K_EXP];             // partial logits
__device__ __align__(16) __half g_xh[(size_t)T_TOK * D_DIM];          // 64 MB
__device__ __align__(16) __half g_wh[(size_t)D_DIM * D_DIM];          // 32 MB
__device__ __align__(16) __half g_ah[(size_t)KR * D_DIM];             //  1 MB
__device__ __align__(16) __half g_Bwh[(size_t)B_DIM * D_DIM * KR];    //  4 MB
__device__ __align__(16) __half g_hh[(size_t)T_TOK * KR];             //  2 MB
__device__ __align__(16) float  g_hp[HSPLIT][(size_t)T_TOK * KR];     // 16 MB

// ---------------- PTX helpers ----------------
__device__ __forceinline__ uint32_t smem_u32(const void* p) {
    uint32_t a;
    asm("{ .reg .u64 t; cvta.to.shared.u64 t, %1; cvt.u32.u64 %0, t; }"
        : "=r"(a) : "l"(p));
    return a;
}

#define CP_ASYNC16(dst, src) \
    asm volatile("cp.async.cg.shared.global [%0], [%1], 16;" \
                 :: "r"(dst), "l"(src) : "memory")
#define CP_COMMIT() asm volatile("cp.async.commit_group;" ::: "memory")
#define CP_WAIT(n)  asm volatile("cp.async.wait_group %0;" :: "n"(n) : "memory")

#define LDSM4(r0, r1, r2, r3, addr) \
    asm volatile("ldmatrix.sync.aligned.m8n8.x4.shared.b16 {%0,%1,%2,%3}, [%4];" \
                 : "=r"(r0), "=r"(r1), "=r"(r2), "=r"(r3) : "r"(addr))

#define MMA16816(d, a, b) \
    asm volatile("mma.sync.aligned.m16n8k16.row.col.f32.f16.f16.f32 " \
                 "{%0,%1,%2,%3},{%4,%5,%6,%7},{%8,%9},{%0,%1,%2,%3};" \
                 : "+f"((d)[0]), "+f"((d)[1]), "+f"((d)[2]), "+f"((d)[3]) \
                 : "r"((a)[0]), "r"((a)[1]), "r"((a)[2]), "r"((a)[3]), \
                   "r"((b)[0]), "r"((b)[1]))

// SW128 swizzle for 128-byte rows
__device__ __forceinline__ uint32_t sw128(uint32_t base, int row, int ch) {
    uint32_t off = (uint32_t)(row * 128 + ch * 16);
    return base + (off ^ ((off >> 3) & 0x70));
}

// ---------------------------------------------------------------------------
// Aux kernels
// ---------------------------------------------------------------------------
__global__ void cvt_f2h_kernel(const float* __restrict__ s, __half* __restrict__ d) {
    size_t i = ((size_t)blockIdx.x * 256 + threadIdx.x) * 4;
    float4 v = *(const float4*)(s + i);
    *(__half2*)(d + i)     = __floats2half2_rn(v.x, v.y);
    *(__half2*)(d + i + 2) = __floats2half2_rn(v.z, v.w);
}

// Fused x fp32->fp16 + column partial sums over 32-row chunks (1024 CTAs).
__global__ void cvt_mean_kernel(const float* __restrict__ x, __half* __restrict__ xh) {
    int d0 = blockIdx.x * 1024 + threadIdx.x * 4;
    int b  = blockIdx.y;
    int c  = blockIdx.z;
    size_t base = ((size_t)(b * S_DIM + c * 32)) * D_DIM + d0;
    float s0 = 0.f, s1 = 0.f, s2 = 0.f, s3 = 0.f;
#pragma unroll 8
    for (int i = 0; i < 32; i++) {
        float4 v = *(const float4*)(x + base + (size_t)i * D_DIM);
        s0 += v.x; s1 += v.y; s2 += v.z; s3 += v.w;
        *(__half2*)(xh + base + (size_t)i * D_DIM)     = __floats2half2_rn(v.x, v.y);
        *(__half2*)(xh + base + (size_t)i * D_DIM + 2) = __floats2half2_rn(v.z, v.w);
    }
    float4 s = { s0, s1, s2, s3 };
    *(float4*)(g_partial + (b * NCHUNK + c) * D_DIM + d0) = s;
}

// Router phase A: partial logits per (b, slice of 256 d-columns)
__global__ void router_a_kernel(const float* __restrict__ rw) {
    int b = blockIdx.x;
    int s = blockIdx.y;
    int tid = threadIdx.x;
    int d = s * 256 + tid;

    float m = 0.f;
#pragma unroll
    for (int c = 0; c < NCHUNK; c++) m += g_partial[(b * NCHUNK + c) * D_DIM + d];
    m *= (1.0f / (float)S_DIM);

    __shared__ float red[256];
#pragma unroll
    for (int k = 0; k < K_EXP; k++) {
        red[tid] = m * rw[k * D_DIM + d];
        __syncthreads();
#pragma unroll
        for (int off = 128; off > 0; off >>= 1) {
            if (tid < off) red[tid] += red[tid + off];
            __syncthreads();
        }
        if (tid == 0) g_lp[(b * 16 + s) * K_EXP + k] = red[0];
        __syncthreads();
    }
}

// bw_kernel with fused router softmax (8-lane shfl groups).
__global__ void bw_kernel(const float* __restrict__ loraB, const float* __restrict__ rb) {
    __shared__ float w[B_DIM * K_EXP];
    if (threadIdx.x < 32) {
        int t = threadIdx.x;
        int b = t >> 3, k = t & 7;
        float s = 0.f;
#pragma unroll
        for (int q = 0; q < 16; q++) s += g_lp[(b * 16 + q) * K_EXP + k];
        s += rb[k];
        float mx = s;
#pragma unroll
        for (int off = 4; off > 0; off >>= 1)
            mx = fmaxf(mx, __shfl_xor_sync(0xffffffffu, mx, off));
        float e = expf(s - mx);
        float sum = e;
#pragma unroll
        for (int off = 4; off > 0; off >>= 1)
            sum += __shfl_xor_sync(0xffffffffu, sum, off);
        w[t] = e / sum;
    }
    __syncthreads();

    int idx = blockIdx.x * 256 + threadIdx.x;           // < 2^21
    int b   = idx >> 19;
    int rem = idx & ((1 << 19) - 1);
    int o   = rem >> 7;
    int c   = rem & 127;
    int k   = c >> 4;
    int r   = c & 15;
    float v = SCALE * w[b * K_EXP + k] * loraB[(k * D_DIM + o) * R_DIM + r];
    g_Bwh[idx] = __float2half_rn(v);
}

// reduce HSPLIT fp32 partial planes of h -> fp16
__global__ void h_reduce_kernel() {
    size_t i = (size_t)blockIdx.x * 256 + threadIdx.x;
    float a0 = 0.f, a1 = 0.f;
#pragma unroll
    for (int p = 0; p < HSPLIT; p++) {
        float2 v = *(const float2*)(g_hp[p] + 2 * i);
        a0 += v.x; a1 += v.y;
    }
    *(__half2*)(g_hh + 2 * i) = __floats2half2_rn(a0, a1);
}

// ---------------------------------------------------------------------------
// h-GEMM: warp tile 64x32, BK=64, 3-stage, split-K z (HSPLIT planes).
// ---------------------------------------------------------------------------
__global__ void __launch_bounds__(128, 2) h_gemm_kernel(
    const __half* __restrict__ A, const __half* __restrict__ Bm,
    float* __restrict__ outf, int iters)
{
    constexpr int BM = 64, BN = 128;
    constexpr int THREADS = 128;
    constexpr int ABYT = BM * 128;
    constexpr int STG  = (BM + BN) * 128;

    extern __shared__ __align__(128) char smem[];
    const uint32_t sbase = smem_u32(smem);
    const int tid  = threadIdx.x;
    const int lane = tid & 31;
    const int wid  = tid >> 5;
    const int wn   = wid;                  // 4 warps over N
    const int i0   = blockIdx.y * BM;
    const int zo   = blockIdx.z * iters * 64;
    A  += zo;
    Bm += zo;
    outf += (size_t)blockIdx.z * ((size_t)T_TOK * KR);

    auto loadst = [&](int git, int st) {
        uint32_t abase = sbase + st * STG;
        uint32_t bbase = abase + ABYT;
        int koff = git * 64;
#pragma unroll
        for (int t = 0; t < (BM * 8) / THREADS; t++) {
            int idx = tid + t * THREADS;
            int row = idx >> 3, ch = idx & 7;
            CP_ASYNC16(sw128(abase, row, ch),
                       A + (size_t)(i0 + row) * D_DIM + koff + ch * 8);
        }
#pragma unroll
        for (int t = 0; t < (BN * 8) / THREADS; t++) {
            int idx = tid + t * THREADS;
            int row = idx >> 3, ch = idx & 7;
            CP_ASYNC16(sw128(bbase, row, ch),
                       Bm + (size_t)row * D_DIM + koff + ch * 8);
        }
    };

    float acc[4][4][4];
#pragma unroll
    for (int mi = 0; mi < 4; mi++)
#pragma unroll
        for (int ni = 0; ni < 4; ni++)
#pragma unroll
            for (int e = 0; e < 4; e++) acc[mi][ni][e] = 0.f;

    loadst(0, 0); CP_COMMIT();
    loadst(1, 1); CP_COMMIT();

    int st = 0, pf = 2;
    for (int it = 0; it < iters; ++it) {
        CP_WAIT(1);
        __syncthreads();
        if (it + 2 < iters) loadst(it + 2, pf);
        CP_COMMIT();

        uint32_t sA = sbase + st * STG;
        uint32_t sB = sA + ABYT;
#pragma unroll
        for (int ks = 0; ks < 4; ks++) {
            int ch = ks * 2 + (lane >> 4);
            uint32_t a[4][4];
#pragma unroll
            for (int mi = 0; mi < 4; mi++) {
                int row = mi * 16 + (lane & 15);
                LDSM4(a[mi][0], a[mi][1], a[mi][2], a[mi][3], sw128(sA, row, ch));
            }
            uint32_t b[4][2];
#pragma unroll
            for (int j = 0; j < 2; j++) {
                int row = wn * 32 + j * 16 + (lane & 15);
                uint32_t t0, t1, t2, t3;
                LDSM4(t0, t1, t2, t3, sw128(sB, row, ch));
                b[2 * j][0]     = t0; b[2 * j][1]     = t2;
                b[2 * j + 1][0] = t1; b[2 * j + 1][1] = t3;
            }
#pragma unroll
            for (int mi = 0; mi < 4; mi++)
#pragma unroll
                for (int ni = 0; ni < 4; ni++)
                    MMA16816(acc[mi][ni], a[mi], b[ni]);
        }
        st = (st == 2) ? 0 : st + 1;
        pf = (pf == 2) ? 0 : pf + 1;
    }

#pragma unroll
    for (int mi = 0; mi < 4; mi++) {
        int r0 = i0 + mi * 16 + (lane >> 2);
#pragma unroll
        for (int ni = 0; ni < 4; ni++) {
            int c0 = wn * 32 + ni * 8 + 2 * (lane & 3);
            float2 v0 = { acc[mi][ni][0], acc[mi][ni][1] };
            float2 v1 = { acc[mi][ni][2], acc[mi][ni][3] };
            *(float2*)(outf + (size_t)r0 * KR + c0)       = v0;
            *(float2*)(outf + (size_t)(r0 + 8) * KR + c0) = v1;
        }
    }
}

// ---------------------------------------------------------------------------
// Main GEMM: BM=128, BN=128, BK=64, 4 warps (2x2 of 64x64), 128 threads,
// 3-stage ring (96 KB) -> 2 CTA/SM (frozen R8/R11 mainloop).
// ---------------------------------------------------------------------------
__global__ void __launch_bounds__(128, 2) main_gemm_kernel(
    const __half* __restrict__ A,
    const __half* __restrict__ Bm,
    const __half* __restrict__ A2,
    const __half* __restrict__ B2all,
    const float* __restrict__ bias,
    float* __restrict__ outf)
{
    constexpr int BM = 128, BN = 128, THREADS = 128;
    constexpr int ITER0 = 64, ITERS = 66;
    constexpr int ABYT = BM * 128;           // 16 KB
    constexpr int STG  = (BM + BN) * 128;    // 32 KB

    extern __shared__ __align__(128) char smem[];
    const uint32_t sbase = smem_u32(smem);
    const int tid  = threadIdx.x;
    const int lane = tid & 31;
    const int wid  = tid >> 5;
    const int wm   = wid & 1;
    const int wn   = wid >> 1;
    const int i0   = blockIdx.y * BM;
    const int j0   = blockIdx.x * BN;
    const __half* B2 = B2all + (size_t)(i0 >> 11) * ((size_t)D_DIM * KR);

    auto loadst = [&](int git, int st) {
        uint32_t abase = sbase + st * STG;
        uint32_t bbase = abase + ABYT;
        const __half* Asrc;
        const __half* Bsrc;
        size_t ld;
        if (git < ITER0) {
            Asrc = A  + (size_t)i0 * D_DIM + git * 64;
            Bsrc = Bm + (size_t)j0 * D_DIM + git * 64;
            ld = D_DIM;
        } else {
            Asrc = A2 + (size_t)i0 * KR + (git - ITER0) * 64;
            Bsrc = B2 + (size_t)j0 * KR + (git - ITER0) * 64;
            ld = KR;
        }
#pragma unroll
        for (int t = 0; t < (BM * 8) / THREADS; t++) {
            int idx = tid + t * THREADS;
            int row = idx >> 3, ch = idx & 7;
            CP_ASYNC16(sw128(abase, row, ch), Asrc + (size_t)row * ld + ch * 8);
        }
#pragma unroll
        for (int t = 0; t < (BN * 8) / THREADS; t++) {
            int idx = tid + t * THREADS;
            int row = idx >> 3, ch = idx & 7;
            CP_ASYNC16(sw128(bbase, row, ch), Bsrc + (size_t)row * ld + ch * 8);
        }
    };

    float acc[4][8][4];
#pragma unroll
    for (int mi = 0; mi < 4; mi++)
#pragma unroll
        for (int ni = 0; ni < 8; ni++)
#pragma unroll
            for (int e = 0; e < 4; e++) acc[mi][ni][e] = 0.f;

    loadst(0, 0); CP_COMMIT();
    loadst(1, 1); CP_COMMIT();

    int st = 0, pf = 2;
    for (int it = 0; it < ITERS; ++it) {
        CP_WAIT(1);
        __syncthreads();
        if (it + 2 < ITERS) loadst(it + 2, pf);
        CP_COMMIT();

        uint32_t sA = sbase + st * STG;
        uint32_t sB = sA + ABYT;
#pragma unroll
        for (int ks = 0; ks < 4; ks++) {
            int ch = ks * 2 + (lane >> 4);
            uint32_t a[4][4];
#pragma unroll
            for (int mi = 0; mi < 4; mi++) {
                int row = wm * 64 + mi * 16 + (lane & 15);
                LDSM4(a[mi][0], a[mi][1], a[mi][2], a[mi][3], sw128(sA, row, ch));
            }
            uint32_t b[8][2];
#pragma unroll
            for (int j = 0; j < 4; j++) {
                int row = wn * 64 + j * 16 + (lane & 15);
                uint32_t t0, t1, t2, t3;
                LDSM4(t0, t1, t2, t3, sw128(sB, row, ch));
                b[2 * j][0]     = t0; b[2 * j][1]     = t2;
                b[2 * j + 1][0] = t1; b[2 * j + 1][1] = t3;
            }
#pragma unroll
            for (int mi = 0; mi < 4; mi++)
#pragma unroll
                for (int ni = 0; ni < 8; ni++)
                    MMA16816(acc[mi][ni], a[mi], b[ni]);
        }
        st = (st == 2) ? 0 : st + 1;
        pf = (pf == 2) ? 0 : pf + 1;
    }

#pragma unroll
    for (int mi = 0; mi < 4; mi++) {
        int r0 = i0 + wm * 64 + mi * 16 + (lane >> 2);
#pragma unroll
        for (int ni = 0; ni < 8; ni++) {
            int c0 = j0 + wn * 64 + ni * 8 + 2 * (lane & 3);
            float b0 = bias[c0], b1 = bias[c0 + 1];
            float2 v0 = { acc[mi][ni][0] + b0, acc[mi][ni][1] + b1 };
            float2 v1 = { acc[mi][ni][2] + b0, acc[mi][ni][3] + b1 };
            *(float2*)(outf + (size_t)r0 * D_DIM + c0)       = v0;
            *(float2*)(outf + (size_t)(r0 + 8) * D_DIM + c0) = v1;
        }
    }
}

// ---------------------------------------------------------------------------
// Host: lazily-created side streams + events (host resources only; device
// work per call is identical and deterministic).
// ---------------------------------------------------------------------------
static cudaStream_t g_s1 = nullptr;
static cudaStream_t g_s2 = nullptr;
static cudaEvent_t  g_e0, g_e1, g_em, g_e2;
static bool         g_streams_ok = false;

extern "C" void kernel_launch(void* const* d_in, const int* in_sizes, int n_in,
                              void* d_out, int out_size) {
    const float* x      = (const float*)d_in[0];   // [4,2048,4096]
    const float* base_w = (const float*)d_in[1];   // [4096,4096]
    const float* base_b = (const float*)d_in[2];   // [4096]
    const float* lora_A = (const float*)d_in[3];   // [8,16,4096]
    const float* lora_B = (const float*)d_in[4];   // [8,4096,16]
    const float* rout_w = (const float*)d_in[5];   // [8,4096]
    const float* rout_b = (const float*)d_in[6];   // [8]
    float* out = (float*)d_out;

    if (g_s1 == nullptr) {
        bool ok = true;
        ok &= (cudaStreamCreateWithFlags(&g_s1, cudaStreamNonBlocking) == cudaSuccess);
        ok &= (cudaStreamCreateWithFlags(&g_s2, cudaStreamNonBlocking) == cudaSuccess);
        ok &= (cudaEventCreateWithFlags(&g_e0, cudaEventDisableTiming) == cudaSuccess);
        ok &= (cudaEventCreateWithFlags(&g_e1, cudaEventDisableTiming) == cudaSuccess);
        ok &= (cudaEventCreateWithFlags(&g_em, cudaEventDisableTiming) == cudaSuccess);
        ok &= (cudaEventCreateWithFlags(&g_e2, cudaEventDisableTiming) == cudaSuccess);
        g_streams_ok = ok;
    }

    const int SMEM_MAIN = 3 * (128 + 128) * 128;   // 98304 -> 2 CTA/SM
    const int SMEM_H    = 3 * (64 + 128) * 128;    // 73728
    cudaFuncSetAttribute(main_gemm_kernel,
                         cudaFuncAttributeMaxDynamicSharedMemorySize, SMEM_MAIN);
    cudaFuncSetAttribute(h_gemm_kernel,
                         cudaFuncAttributeMaxDynamicSharedMemorySize, SMEM_H);

    __half* xh;  cudaGetSymbolAddress((void**)&xh,  g_xh);
    __half* wh;  cudaGetSymbolAddress((void**)&wh,  g_wh);
    __half* ah;  cudaGetSymbolAddress((void**)&ah,  g_ah);
    __half* bwh; cudaGetSymbolAddress((void**)&bwh, g_Bwh);
    __half* hh;  cudaGetSymbolAddress((void**)&hh,  g_hh);
    float*  hp;  cudaGetSymbolAddress((void**)&hp,  g_hp);

    cudaStream_t s0 = (cudaStream_t)0;
    cudaStream_t sW = g_streams_ok ? g_s1 : s0;
    cudaStream_t sR = g_streams_ok ? g_s2 : s0;

    if (g_streams_ok) {
        cudaEventRecord(g_e0, s0);
        cudaStreamWaitEvent(sW, g_e0, 0);
    }

    // sW: W fp32 -> fp16 (independent)
    cvt_f2h_kernel<<<((size_t)D_DIM * D_DIM) / 1024, 256, 0, sW>>>(base_w, wh);
    if (g_streams_ok) cudaEventRecord(g_e1, sW);

    // s0: x convert + mean partials (critical path), 1024 CTAs
    cvt_mean_kernel<<<dim3(D_DIM / 1024, B_DIM, NCHUNK), 256, 0, s0>>>(x, xh);

    if (g_streams_ok) {
        cudaEventRecord(g_em, s0);
        cudaStreamWaitEvent(sR, g_em, 0);
    }
    // sR: router logits + fused softmax + Bw build
    router_a_kernel<<<dim3(B_DIM, 16), 256, 0, sR>>>(rout_w);
    bw_kernel<<<(B_DIM * D_DIM * KR) / 256, 256, 0, sR>>>(lora_B, rout_b);
    if (g_streams_ok) cudaEventRecord(g_e2, sR);

    // s0: lora_A convert + h = x @ A_cat^T (split-K4) + reduce
    cvt_f2h_kernel<<<((size_t)KR * D_DIM) / 1024, 256, 0, s0>>>(lora_A, ah);
    h_gemm_kernel<<<dim3(1, T_TOK / 64, HSPLIT), 128, SMEM_H, s0>>>(xh, ah, hp, 64 / HSPLIT);
    h_reduce_kernel<<<(T_TOK * KR / 2) / 256, 256, 0, s0>>>();

    if (g_streams_ok) {
        cudaStreamWaitEvent(s0, g_e1, 0);
        cudaStreamWaitEvent(s0, g_e2, 0);
    }

    // out = x @ W^T + h @ Bw^T + bias
    main_gemm_kernel<<<dim3(D_DIM / 128, T_TOK / 128), 128, SMEM_MAIN, s0>>>(
        xh, wh, hh, bwh, base_b, out);
}